// round 14
// baseline (speedup 1.0000x reference)
#include <cuda_runtime.h>
#include <cuda_bf16.h>
#include <math.h>
#include <stdint.h>

#define N_PROP 1024
#define C_FEAT 32
#define ROI 7
#define SR 6
#define SS 42
#define D_FEAT 1568
#define HID 2048
#define NMS_K 100
#define OUT_TOTAL 2600
#define NMS_THRF 0.01f
#define IMG_H 360
#define IMG_W 1200
#define BEV_H 700
#define BEV_W 800
#define IMG_HW (IMG_H * IMG_W)
#define BEV_HW (BEV_H * BEV_W)
#define X_MIN (-40.0f)
#define Z_MAX (70.0f)
#define VOX (0.1f)

__device__ float g_imgbox[N_PROP * 4];
__device__ float g_bevbox[N_PROP * 4];
__device__ float g_imgT[IMG_HW * C_FEAT];
__device__ float g_bevT[BEV_HW * C_FEAT];
__device__ float g_roiA[N_PROP * D_FEAT];
__device__ float g_roiB[N_PROP * D_FEAT];
__device__ float g_h2[N_PROP * HID];
__device__ float g_heads[N_PROP * 14];
__device__ float g_obj_soft[N_PROP * 2];
__device__ float g_pred[N_PROP * 6];
__device__ float g_predbev[N_PROP * 4];
__device__ float g_scores[N_PROP];
__device__ float g_orient[N_PROP];
__device__ int   g_idx[NMS_K];

__device__ unsigned short g_W1h[D_FEAT * HID];
__device__ unsigned short g_W1l[D_FEAT * HID];
__device__ unsigned short g_W2h[HID * HID];
__device__ unsigned short g_W2l[HID * HID];
__device__ unsigned short g_A1h[N_PROP * D_FEAT];
__device__ unsigned short g_A1l[N_PROP * D_FEAT];
__device__ unsigned short g_H1h[N_PROP * HID];
__device__ unsigned short g_H1l[N_PROP * HID];

__device__ __forceinline__ uint32_t smem_u32(const void* p) {
    uint32_t a;
    asm("{ .reg .u64 t; cvta.to.shared.u64 t, %1; cvt.u32.u64 %0, t; }" : "=r"(a) : "l"(p));
    return a;
}
#define CP16(d, s) asm volatile("cp.async.cg.shared.global [%0], [%1], 16;" :: "r"(d), "l"(s))
#define CP_COMMIT() asm volatile("cp.async.commit_group;" ::: "memory")
#define CP_WAIT_0() asm volatile("cp.async.wait_group 0;" ::: "memory")

#define LDSM_X4(r0, r1, r2, r3, a) \
    asm volatile("ldmatrix.sync.aligned.m8n8.x4.shared.b16 {%0,%1,%2,%3}, [%4];" \
        : "=r"(r0), "=r"(r1), "=r"(r2), "=r"(r3) : "r"(a))
#define LDSM_X4T(r0, r1, r2, r3, a) \
    asm volatile("ldmatrix.sync.aligned.m8n8.x4.trans.shared.b16 {%0,%1,%2,%3}, [%4];" \
        : "=r"(r0), "=r"(r1), "=r"(r2), "=r"(r3) : "r"(a))
#define MMA16816(c, a0, a1, a2, a3, b0, b1) \
    asm volatile("mma.sync.aligned.m16n8k16.row.col.f32.bf16.bf16.f32 " \
        "{%0,%1,%2,%3}, {%4,%5,%6,%7}, {%8,%9}, {%0,%1,%2,%3};" \
        : "+f"((c)[0]), "+f"((c)[1]), "+f"((c)[2]), "+f"((c)[3]) \
        : "r"(a0), "r"(a1), "r"(a2), "r"(a3), "r"(b0), "r"(b1))

__device__ __forceinline__ void bsplit(float x, unsigned short& h, unsigned short& l) {
    __nv_bfloat16 bh = __float2bfloat16(x);
    float r = x - __bfloat162float(bh);
    __nv_bfloat16 bl = __float2bfloat16(r);
    h = *reinterpret_cast<unsigned short*>(&bh);
    l = *reinterpret_cast<unsigned short*>(&bl);
}

// ---------------- projections -------------------------------------------------
__global__ void project_kernel(const float* __restrict__ anchors,
                               const float* __restrict__ calib,
                               const int* __restrict__ image_shape)
{
    int n = blockIdx.x * blockDim.x + threadIdx.x;
    if (n >= N_PROP) return;
    const float* a = anchors + n * 6;
    float x = a[0], y = a[1], z = a[2];
    float dx = a[3], dy = a[4], dz = a[5];
    g_bevbox[n*4+0] = (x - dx*0.5f - X_MIN) / VOX;
    g_bevbox[n*4+1] = (Z_MAX - (z + dz*0.5f)) / VOX;
    g_bevbox[n*4+2] = (x + dx*0.5f - X_MIN) / VOX;
    g_bevbox[n*4+3] = (Z_MAX - (z - dz*0.5f)) / VOX;

    float P[12];
#pragma unroll
    for (int i = 0; i < 12; i++) P[i] = calib[i];
    float Hf = (float)image_shape[0];
    float Wf = (float)image_shape[1];
    float umin = 1e30f, umax = -1e30f, vmin = 1e30f, vmax = -1e30f;
#pragma unroll
    for (int k = 0; k < 8; k++) {
        float sx = (k & 4) ? 1.f : -1.f;
        float sy = (k & 2) ? 1.f : -1.f;
        float sz = (k & 1) ? 1.f : -1.f;
        float cx = x + sx * dx * 0.5f;
        float cy = y + sy * dy * 0.5f;
        float cz = z + sz * dz * 0.5f;
        float px = P[0]*cx + P[1]*cy + P[2]*cz + P[3];
        float py = P[4]*cx + P[5]*cy + P[6]*cz + P[7];
        float pz = P[8]*cx + P[9]*cy + P[10]*cz + P[11];
        float zz = fmaxf(pz, 0.1f);
        float u = px / zz, v = py / zz;
        umin = fminf(umin, u); umax = fmaxf(umax, u);
        vmin = fminf(vmin, v); vmax = fmaxf(vmax, v);
    }
    g_imgbox[n*4+0] = fminf(fmaxf(umin, 0.f), Wf);
    g_imgbox[n*4+1] = fminf(fmaxf(vmin, 0.f), Hf);
    g_imgbox[n*4+2] = fminf(fmaxf(umax, 0.f), Wf);
    g_imgbox[n*4+3] = fminf(fmaxf(vmax, 0.f), Hf);
}

// ---------------- CHW -> HWC transpose ----------------------------------------
#define IMG_TILES (IMG_HW / 64)
#define BEV_TILES (BEV_HW / 64)
__global__ void transpose_kernel(const float* __restrict__ img,
                                 const float* __restrict__ bev)
{
    int b = blockIdx.x;
    const float* src;
    float* dst;
    int HW, p0;
    if (b < IMG_TILES) { src = img; dst = g_imgT; HW = IMG_HW; p0 = b * 64; }
    else               { src = bev; dst = g_bevT; HW = BEV_HW; p0 = (b - IMG_TILES) * 64; }
    __shared__ float tile[32][65];
    int t = threadIdx.x;
#pragma unroll
    for (int i = 0; i < 2; i++) {
        int idx = t + i * 256;
        int c = idx >> 4, v4 = idx & 15;
        float4 v = *reinterpret_cast<const float4*>(src + (size_t)c * HW + p0 + v4 * 4);
        tile[c][v4*4+0] = v.x; tile[c][v4*4+1] = v.y;
        tile[c][v4*4+2] = v.z; tile[c][v4*4+3] = v.w;
    }
    __syncthreads();
#pragma unroll
    for (int i = 0; i < 2; i++) {
        int idx = t + i * 256;
        int p = idx >> 3, c4 = idx & 7;
        float4 v;
        v.x = tile[c4*4+0][p]; v.y = tile[c4*4+1][p];
        v.z = tile[c4*4+2][p]; v.w = tile[c4*4+3][p];
        *reinterpret_cast<float4*>(dst + (size_t)(p0 + p) * 32 + c4 * 4) = v;
    }
}

// ---------------- ROI align: 2048 blocks, low-reg, incremental indices ---------
__global__ __launch_bounds__(256, 6)
void roi_kernel()
{
    int b = blockIdx.x;
    int isImg = (b < N_PROP);
    int n = b & (N_PROP - 1);

    const float* ft    = isImg ? g_imgT : g_bevT;
    const float* boxes = isImg ? g_imgbox : g_bevbox;
    float* outp        = isImg ? g_roiA : g_roiB;
    int H = isImg ? IMG_H : BEV_H;
    int W = isImg ? IMG_W : BEV_W;

    __shared__ int2  sxp[SS];
    __shared__ int2  syp[SS];
    __shared__ float swx[SS], swy[SS];
    __shared__ float sout[D_FEAT];
    int t = threadIdx.x;
    int warp = t >> 5, lane = t & 31;
    int sg = lane >> 3;
    int c4 = (lane & 7) * 4;

    if (t < SS) {
        float bx1 = boxes[n*4+0] - 0.5f;
        float bx2 = boxes[n*4+2] - 0.5f;
        float g = ((float)t + 0.5f) / (float)SS;
        float xs = bx1 + g * (bx2 - bx1);
        float xf = fminf(fmaxf(floorf(xs), 0.f), (float)(W - 1));
        swx[t] = fminf(fmaxf(xs - xf, 0.f), 1.f);
        int xi = (int)xf;
        sxp[t] = make_int2(xi * 32, min(xi + 1, W - 1) * 32);
    } else if (t < 2 * SS) {
        int tt = t - SS;
        float by1 = boxes[n*4+1] - 0.5f;
        float by2 = boxes[n*4+3] - 0.5f;
        float g = ((float)tt + 0.5f) / (float)SS;
        float ys = by1 + g * (by2 - by1);
        float yf = fminf(fmaxf(floorf(ys), 0.f), (float)(H - 1));
        swy[tt] = fminf(fmaxf(ys - yf, 0.f), 1.f);
        int yi = (int)yf;
        syp[tt] = make_int2(yi * W * 32, min(yi + 1, H - 1) * W * 32);
    }
    __syncthreads();

    const float* fb = ft + c4;
    for (int bin = warp; bin < ROI * ROI; bin += 8) {
        int py = (bin / ROI) * SR;
        int px = (bin % ROI) * SR;
        float ax = 0.f, ay = 0.f, az = 0.f, aw = 0.f;
        int iy = 0, ix = sg;    // incremental sample index: s = it*4 + sg
#pragma unroll
        for (int it = 0; it < 9; it++) {
            int gy = py + iy, gx = px + ix;
            int2 ro = syp[gy];
            float wy = swy[gy];
            int2 xx = sxp[gx];
            float wx = swx[gx];
            float4 f00 = *reinterpret_cast<const float4*>(fb + ro.x + xx.x);
            float4 f01 = *reinterpret_cast<const float4*>(fb + ro.x + xx.y);
            float4 f10 = *reinterpret_cast<const float4*>(fb + ro.y + xx.x);
            float4 f11 = *reinterpret_cast<const float4*>(fb + ro.y + xx.y);
            float tx0, bx0;
            tx0 = fmaf(f01.x - f00.x, wx, f00.x);
            bx0 = fmaf(f11.x - f10.x, wx, f10.x);
            ax += fmaf(bx0 - tx0, wy, tx0);
            tx0 = fmaf(f01.y - f00.y, wx, f00.y);
            bx0 = fmaf(f11.y - f10.y, wx, f10.y);
            ay += fmaf(bx0 - tx0, wy, tx0);
            tx0 = fmaf(f01.z - f00.z, wx, f00.z);
            bx0 = fmaf(f11.z - f10.z, wx, f10.z);
            az += fmaf(bx0 - tx0, wy, tx0);
            tx0 = fmaf(f01.w - f00.w, wx, f00.w);
            bx0 = fmaf(f11.w - f10.w, wx, f10.w);
            aw += fmaf(bx0 - tx0, wy, tx0);
            ix += 4;
            if (ix >= SR) { ix -= SR; iy += 1; }
        }
#pragma unroll
        for (int off = 16; off >= 8; off >>= 1) {
            ax += __shfl_down_sync(0xffffffffu, ax, off);
            ay += __shfl_down_sync(0xffffffffu, ay, off);
            az += __shfl_down_sync(0xffffffffu, az, off);
            aw += __shfl_down_sync(0xffffffffu, aw, off);
        }
        if (lane < 8) {
            int ch = lane * 4;
            sout[(ch+0) * 49 + bin] = ax * (1.f / 36.f);
            sout[(ch+1) * 49 + bin] = ay * (1.f / 36.f);
            sout[(ch+2) * 49 + bin] = az * (1.f / 36.f);
            sout[(ch+3) * 49 + bin] = aw * (1.f / 36.f);
        }
    }
    __syncthreads();

    float* dst = outp + (size_t)n * D_FEAT;
    for (int idx = t; idx < D_FEAT; idx += 256)
        dst[idx] = sout[idx];
}

// ---------------- fuse + bf16 split (roiA, roiB -> A1h/A1l) --------------------
#define PA_N (N_PROP * D_FEAT / 4)
__global__ void prep_ab_kernel(const float* __restrict__ mi,
                               const float* __restrict__ mb)
{
    int i = blockIdx.x * blockDim.x + threadIdx.x;
    if (i >= PA_N) return;
    float ma = mi[0], mbv = mb[0];
    float inv = 1.f / (ma + mbv);
    float4 a = reinterpret_cast<const float4*>(g_roiA)[i];
    float4 bb = reinterpret_cast<const float4*>(g_roiB)[i];
    float4 v;
    v.x = (a.x * ma + bb.x * mbv) * inv;
    v.y = (a.y * ma + bb.y * mbv) * inv;
    v.z = (a.z * ma + bb.z * mbv) * inv;
    v.w = (a.w * ma + bb.w * mbv) * inv;
    unsigned short h0, l0, h1, l1, h2, l2, h3, l3;
    bsplit(v.x, h0, l0); bsplit(v.y, h1, l1);
    bsplit(v.z, h2, l2); bsplit(v.w, h3, l3);
    uint2 ph = { (uint32_t)h0 | ((uint32_t)h1 << 16), (uint32_t)h2 | ((uint32_t)h3 << 16) };
    uint2 pl = { (uint32_t)l0 | ((uint32_t)l1 << 16), (uint32_t)l2 | ((uint32_t)l3 << 16) };
    reinterpret_cast<uint2*>(g_A1h)[i] = ph;
    reinterpret_cast<uint2*>(g_A1l)[i] = pl;
}

// ---------------- weight split prep --------------------------------------------
#define PW_N1 (D_FEAT * HID / 4)
#define PW_N2 (HID * HID / 4)
__global__ void prep_w_kernel(const float* __restrict__ W1, const float* __restrict__ W2)
{
    int i = blockIdx.x * blockDim.x + threadIdx.x;
    const float4* src;
    unsigned short *dh, *dl;
    int idx;
    if (i < PW_N1) {
        src = reinterpret_cast<const float4*>(W1);
        dh = g_W1h; dl = g_W1l; idx = i;
    } else if (i < PW_N1 + PW_N2) {
        src = reinterpret_cast<const float4*>(W2);
        dh = g_W2h; dl = g_W2l; idx = i - PW_N1;
    } else return;
    float4 v = src[idx];
    unsigned short h0, l0, h1, l1, h2, l2, h3, l3;
    bsplit(v.x, h0, l0); bsplit(v.y, h1, l1);
    bsplit(v.z, h2, l2); bsplit(v.w, h3, l3);
    uint2 ph = { (uint32_t)h0 | ((uint32_t)h1 << 16), (uint32_t)h2 | ((uint32_t)h3 << 16) };
    uint2 pl = { (uint32_t)l0 | ((uint32_t)l1 << 16), (uint32_t)l2 | ((uint32_t)l3 << 16) };
    reinterpret_cast<uint2*>(dh)[idx] = ph;
    reinterpret_cast<uint2*>(dl)[idx] = pl;
}

// ---------------- HMMA bf16x3 GEMM, all-cp.async operands ----------------------
#define GA_ST 10240
#define GB_ST 4608
#define OFF_AH 0
#define OFF_AL (2 * GA_ST)
#define OFF_BH (4 * GA_ST)
#define OFF_BL (4 * GA_ST + 2 * GB_ST)
#define GEMM_SMEM (4 * GA_ST + 4 * GB_ST)

template<int SPLIT_OUT>
__global__ __launch_bounds__(256)
void mma_gemm(const unsigned short* __restrict__ Ah, const unsigned short* __restrict__ Al,
              const unsigned short* __restrict__ Wh, const unsigned short* __restrict__ Wl,
              const float* __restrict__ bias, float* __restrict__ C,
              unsigned short* __restrict__ Oh, unsigned short* __restrict__ Ol, int K)
{
    extern __shared__ char smem[];
    uint32_t sb = smem_u32(smem);
    int tid = threadIdx.x;
    int wid = tid >> 5, lane = tid & 31;
    int wm = wid >> 2, wn = wid & 3;
    int m0 = blockIdx.y * 128, n0 = blockIdx.x * 64;

    int a_row0 = tid >> 2, a_seg0 = tid & 3;
    int a_row1 = (tid + 256) >> 2, a_seg1 = (tid + 256) & 3;
    int b_kk = tid >> 3;
    int b_ch = (tid & 7) << 3;

    float acc[4][2][4];
#pragma unroll
    for (int i = 0; i < 4; i++)
#pragma unroll
        for (int j = 0; j < 2; j++)
#pragma unroll
            for (int r = 0; r < 4; r++) acc[i][j][r] = 0.f;

    int ntiles = K / 32;

    auto issue = [&](int k0, int stage) {
        uint32_t ah = sb + OFF_AH + stage * GA_ST;
        uint32_t al = sb + OFF_AL + stage * GA_ST;
        CP16(ah + a_row0 * 80 + a_seg0 * 16, Ah + (size_t)(m0 + a_row0) * K + k0 + a_seg0 * 8);
        CP16(ah + a_row1 * 80 + a_seg1 * 16, Ah + (size_t)(m0 + a_row1) * K + k0 + a_seg1 * 8);
        CP16(al + a_row0 * 80 + a_seg0 * 16, Al + (size_t)(m0 + a_row0) * K + k0 + a_seg0 * 8);
        CP16(al + a_row1 * 80 + a_seg1 * 16, Al + (size_t)(m0 + a_row1) * K + k0 + a_seg1 * 8);
        uint32_t boff = (uint32_t)(b_kk * 144 + b_ch * 2);
        CP16(sb + OFF_BH + stage * GB_ST + boff, Wh + (size_t)(k0 + b_kk) * HID + n0 + b_ch);
        CP16(sb + OFF_BL + stage * GB_ST + boff, Wl + (size_t)(k0 + b_kk) * HID + n0 + b_ch);
        CP_COMMIT();
    };

    issue(0, 0);
    CP_WAIT_0();
    __syncthreads();

    int lr = lane & 15;
    int lhalf = (lane >> 4) << 3;

    for (int t = 0; t < ntiles; t++) {
        int stage = t & 1;
        bool more = (t + 1 < ntiles);
        if (more) issue((t + 1) * 32, stage ^ 1);

        uint32_t aH = sb + OFF_AH + stage * GA_ST;
        uint32_t aL = sb + OFF_AL + stage * GA_ST;
        uint32_t bH = sb + OFF_BH + stage * GB_ST;
        uint32_t bL = sb + OFF_BL + stage * GB_ST;

#pragma unroll
        for (int ks = 0; ks < 2; ks++) {
            uint32_t bo = (uint32_t)((ks * 16 + lr) * 144 + (wn * 16 + lhalf) * 2);
            uint32_t bh0, bh1, bh2, bh3, bl0, bl1, bl2, bl3;
            LDSM_X4T(bh0, bh1, bh2, bh3, bH + bo);
            LDSM_X4T(bl0, bl1, bl2, bl3, bL + bo);
#pragma unroll
            for (int mt = 0; mt < 4; mt++) {
                uint32_t ao = (uint32_t)((wm * 64 + mt * 16 + lr) * 80 +
                                         (ks * 16 + lhalf) * 2);
                uint32_t ah0, ah1, ah2, ah3, al0, al1, al2, al3;
                LDSM_X4(ah0, ah1, ah2, ah3, aH + ao);
                LDSM_X4(al0, al1, al2, al3, aL + ao);
                MMA16816(acc[mt][0], ah0, ah1, ah2, ah3, bh0, bh1);
                MMA16816(acc[mt][1], ah0, ah1, ah2, ah3, bh2, bh3);
                MMA16816(acc[mt][0], ah0, ah1, ah2, ah3, bl0, bl1);
                MMA16816(acc[mt][1], ah0, ah1, ah2, ah3, bl2, bl3);
                MMA16816(acc[mt][0], al0, al1, al2, al3, bh0, bh1);
                MMA16816(acc[mt][1], al0, al1, al2, al3, bh2, bh3);
            }
        }

        if (more) {
            CP_WAIT_0();
            __syncthreads();
        }
    }

#pragma unroll
    for (int mt = 0; mt < 4; mt++) {
        int r = m0 + wm * 64 + mt * 16 + (lane >> 2);
#pragma unroll
        for (int nt = 0; nt < 2; nt++) {
            int c = n0 + wn * 16 + nt * 8 + 2 * (lane & 3);
            float2 bv = *reinterpret_cast<const float2*>(bias + c);
            float v00 = fmaxf(acc[mt][nt][0] + bv.x, 0.f);
            float v01 = fmaxf(acc[mt][nt][1] + bv.y, 0.f);
            float v10 = fmaxf(acc[mt][nt][2] + bv.x, 0.f);
            float v11 = fmaxf(acc[mt][nt][3] + bv.y, 0.f);
            if (SPLIT_OUT) {
                unsigned short h0, l0, h1, l1;
                bsplit(v00, h0, l0); bsplit(v01, h1, l1);
                *reinterpret_cast<uint32_t*>(Oh + (size_t)r * HID + c) =
                    (uint32_t)h0 | ((uint32_t)h1 << 16);
                *reinterpret_cast<uint32_t*>(Ol + (size_t)r * HID + c) =
                    (uint32_t)l0 | ((uint32_t)l1 << 16);
                bsplit(v10, h0, l0); bsplit(v11, h1, l1);
                *reinterpret_cast<uint32_t*>(Oh + (size_t)(r + 8) * HID + c) =
                    (uint32_t)h0 | ((uint32_t)h1 << 16);
                *reinterpret_cast<uint32_t*>(Ol + (size_t)(r + 8) * HID + c) =
                    (uint32_t)l0 | ((uint32_t)l1 << 16);
            } else {
                float2 o0 = {v00, v01}, o1 = {v10, v11};
                *reinterpret_cast<float2*>(C + (size_t)r * HID + c) = o0;
                *reinterpret_cast<float2*>(C + (size_t)(r + 8) * HID + c) = o1;
            }
        }
    }
}

// ---------------- heads --------------------------------------------------------
__global__ void heads_kernel(const float* __restrict__ Wc, const float* __restrict__ bc,
                             const float* __restrict__ Wo, const float* __restrict__ bo,
                             const float* __restrict__ Wa, const float* __restrict__ ba)
{
    int warp = threadIdx.x >> 5;
    int lane = threadIdx.x & 31;
    int row = blockIdx.x * 8 + warp;
    const float2* Wc2 = reinterpret_cast<const float2*>(Wc);
    const float2* Wo2 = reinterpret_cast<const float2*>(Wo);
    const float2* Wa2 = reinterpret_cast<const float2*>(Wa);
    float acc[14];
#pragma unroll
    for (int c = 0; c < 14; c++) acc[c] = 0.f;
    const float* h = g_h2 + (size_t)row * HID;
    for (int k = lane; k < HID; k += 32) {
        float hv = h[k];
        float2 cw = Wc2[k];
        acc[0] = fmaf(hv, cw.x, acc[0]);
        acc[1] = fmaf(hv, cw.y, acc[1]);
        const float2* wo = Wo2 + (size_t)k * 5;
#pragma unroll
        for (int j = 0; j < 5; j++) {
            float2 ov = wo[j];
            acc[2 + 2*j]     = fmaf(hv, ov.x, acc[2 + 2*j]);
            acc[2 + 2*j + 1] = fmaf(hv, ov.y, acc[2 + 2*j + 1]);
        }
        float2 aw = Wa2[k];
        acc[12] = fmaf(hv, aw.x, acc[12]);
        acc[13] = fmaf(hv, aw.y, acc[13]);
    }
#pragma unroll
    for (int c = 0; c < 14; c++) {
#pragma unroll
        for (int off = 16; off > 0; off >>= 1)
            acc[c] += __shfl_down_sync(0xffffffffu, acc[c], off);
    }
    if (lane == 0) {
#pragma unroll
        for (int c = 0; c < 14; c++) {
            float b = (c < 2) ? bc[c] : (c < 12 ? bo[c-2] : ba[c-12]);
            g_heads[row*14 + c] = acc[c] + b;
        }
    }
}

// ---------------- post ----------------------------------------------------------
__global__ void post_kernel(const float* __restrict__ anchors)
{
    int n = blockIdx.x * blockDim.x + threadIdx.x;
    if (n >= N_PROP) return;
    const float* hd = g_heads + n * 14;
    float o0 = hd[0], o1 = hd[1];
    float m = fmaxf(o0, o1);
    float e0 = expf(o0 - m), e1 = expf(o1 - m);
    float inv = 1.f / (e0 + e1);
    g_obj_soft[n*2+0] = e0 * inv;
    g_obj_soft[n*2+1] = e1 * inv;
    g_scores[n] = o1;
    g_orient[n] = atan2f(hd[13], hd[12]);
    float p[6];
#pragma unroll
    for (int i = 0; i < 6; i++) {
        p[i] = anchors[n*6+i] + hd[2+i];
        g_pred[n*6+i] = p[i];
    }
    float x = p[0], z = p[2], dx = p[3], dz = p[5];
    g_predbev[n*4+0] = (x - dx*0.5f - X_MIN) / VOX;
    g_predbev[n*4+1] = (Z_MAX - (z + dz*0.5f)) / VOX;
    g_predbev[n*4+2] = (x + dx*0.5f - X_MIN) / VOX;
    g_predbev[n*4+3] = (Z_MAX - (z - dz*0.5f)) / VOX;
}

// ---------------- NMS -----------------------------------------------------------
__global__ void nms_kernel()
{
    int t = threadIdx.x;
    __shared__ float ss[N_PROP];
    __shared__ float sval[8];
    __shared__ int   sidx[8];
    __shared__ float sb[4];
    __shared__ int   scur;
    float bx1[4], by1[4], bx2[4], by2[4], bar[4];
#pragma unroll
    for (int i = 0; i < 4; i++) {
        int b = t + i * 256;
        bx1[i] = g_predbev[b*4+0];
        by1[i] = g_predbev[b*4+1];
        bx2[i] = g_predbev[b*4+2];
        by2[i] = g_predbev[b*4+3];
        bar[i] = (bx2[i] - bx1[i]) * (by2[i] - by1[i]);
        ss[b] = g_scores[b];
    }
    __syncthreads();
    int warp = t >> 5, lane = t & 31;
    for (int k = 0; k < NMS_K; k++) {
        float v = -INFINITY;
        int bi = N_PROP;
#pragma unroll
        for (int i = 0; i < 4; i++) {
            int b = t + i * 256;
            float s = ss[b];
            if (s > v) { v = s; bi = b; }
        }
#pragma unroll
        for (int off = 16; off > 0; off >>= 1) {
            float ov = __shfl_down_sync(0xffffffffu, v, off);
            int   oi = __shfl_down_sync(0xffffffffu, bi, off);
            if (ov > v || (ov == v && oi < bi)) { v = ov; bi = oi; }
        }
        if (lane == 0) { sval[warp] = v; sidx[warp] = bi; }
        __syncthreads();
        if (t < 8) {
            v = sval[t]; bi = sidx[t];
#pragma unroll
            for (int off = 4; off > 0; off >>= 1) {
                float ov = __shfl_down_sync(0xffu, v, off, 8);
                int   oi = __shfl_down_sync(0xffu, bi, off, 8);
                if (ov > v || (ov == v && oi < bi)) { v = ov; bi = oi; }
            }
            if (t == 0) {
                scur = bi;
                g_idx[k] = bi;
                sb[0] = g_predbev[bi*4+0];
                sb[1] = g_predbev[bi*4+1];
                sb[2] = g_predbev[bi*4+2];
                sb[3] = g_predbev[bi*4+3];
            }
        }
        __syncthreads();
        float px1 = sb[0], py1 = sb[1], px2 = sb[2], py2 = sb[3];
        float parea = (px2 - px1) * (py2 - py1);
        int cur = scur;
#pragma unroll
        for (int i = 0; i < 4; i++) {
            int b = t + i * 256;
            float xx1 = fmaxf(bx1[i], px1);
            float yy1 = fmaxf(by1[i], py1);
            float xx2 = fminf(bx2[i], px2);
            float yy2 = fminf(by2[i], py2);
            float inter = fmaxf(xx2 - xx1, 0.f) * fmaxf(yy2 - yy1, 0.f);
            float iou = inter / (bar[i] + parea - inter + 1e-6f);
            if (iou > NMS_THRF || b == cur) ss[b] = -INFINITY;
        }
        __syncthreads();
    }
}

// ---------------- gather --------------------------------------------------------
__global__ void gather_kernel(float* __restrict__ out)
{
    int i = blockIdx.x * blockDim.x + threadIdx.x;
    if (i >= OUT_TOTAL) return;
    float v;
    if (i < 200) {
        int n = i / 2, c = i % 2;
        v = g_obj_soft[g_idx[n]*2 + c];
    } else if (i < 800) {
        int j = i - 200; int n = j / 6, c = j % 6;
        v = g_pred[g_idx[n]*6 + c];
    } else if (i < 1800) {
        int j = i - 800; int n = j / 10, c = j % 10;
        v = g_heads[g_idx[n]*14 + 2 + c];
    } else if (i < 2500) {
        int j = i - 1800; int n = j / 7, c = j % 7;
        v = (c < 6) ? g_pred[g_idx[n]*6 + c] : 0.f;
    } else {
        int n = i - 2500;
        v = g_orient[g_idx[n]];
    }
    out[i] = v;
}

// ---------------- launch ---------------------------------------------------------
extern "C" void kernel_launch(void* const* d_in, const int* in_sizes, int n_in,
                              void* d_out, int out_size)
{
    const float* img_feat = (const float*)d_in[0];
    const float* bev_feat = (const float*)d_in[1];
    const float* anchors  = (const float*)d_in[2];
    const float* calib    = (const float*)d_in[3];
    const float* img_mask = (const float*)d_in[5];
    const float* bev_mask = (const float*)d_in[6];
    const float* W1 = (const float*)d_in[7];
    const float* b1 = (const float*)d_in[8];
    const float* W2 = (const float*)d_in[9];
    const float* b2 = (const float*)d_in[10];
    const float* Wc = (const float*)d_in[11];
    const float* bc = (const float*)d_in[12];
    const float* Wo = (const float*)d_in[13];
    const float* bo = (const float*)d_in[14];
    const float* Wa = (const float*)d_in[15];
    const float* ba = (const float*)d_in[16];
    const int* image_shape = (const int*)d_in[17];
    float* out = (float*)d_out;

    void *pH2, *pW1h, *pW1l, *pW2h, *pW2l, *pA1h, *pA1l, *pH1h, *pH1l;
    cudaGetSymbolAddress(&pH2, g_h2);
    cudaGetSymbolAddress(&pW1h, g_W1h);
    cudaGetSymbolAddress(&pW1l, g_W1l);
    cudaGetSymbolAddress(&pW2h, g_W2h);
    cudaGetSymbolAddress(&pW2l, g_W2l);
    cudaGetSymbolAddress(&pA1h, g_A1h);
    cudaGetSymbolAddress(&pA1l, g_A1l);
    cudaGetSymbolAddress(&pH1h, g_H1h);
    cudaGetSymbolAddress(&pH1l, g_H1l);

    cudaFuncSetAttribute(mma_gemm<0>, cudaFuncAttributeMaxDynamicSharedMemorySize, GEMM_SMEM);
    cudaFuncSetAttribute(mma_gemm<1>, cudaFuncAttributeMaxDynamicSharedMemorySize, GEMM_SMEM);

    project_kernel<<<8, 128>>>(anchors, calib, image_shape);
    transpose_kernel<<<IMG_TILES + BEV_TILES, 256>>>(img_feat, bev_feat);
    prep_w_kernel<<<(PW_N1 + PW_N2 + 255) / 256, 256>>>(W1, W2);
    roi_kernel<<<2 * N_PROP, 256>>>();
    prep_ab_kernel<<<(PA_N + 255) / 256, 256>>>(img_mask, bev_mask);

    dim3 gg(HID / 64, N_PROP / 128);
    mma_gemm<1><<<gg, 256, GEMM_SMEM>>>(
        (const unsigned short*)pA1h, (const unsigned short*)pA1l,
        (const unsigned short*)pW1h, (const unsigned short*)pW1l,
        b1, nullptr, (unsigned short*)pH1h, (unsigned short*)pH1l, D_FEAT);
    mma_gemm<0><<<gg, 256, GEMM_SMEM>>>(
        (const unsigned short*)pH1h, (const unsigned short*)pH1l,
        (const unsigned short*)pW2h, (const unsigned short*)pW2l,
        b2, (float*)pH2, nullptr, nullptr, HID);

    heads_kernel<<<N_PROP / 8, 256>>>(Wc, bc, Wo, bo, Wa, ba);
    post_kernel<<<8, 128>>>(anchors);
    nms_kernel<<<1, 256>>>();
    gather_kernel<<<(OUT_TOTAL + 255) / 256, 256>>>(out);
}

// round 15
// speedup vs baseline: 1.0189x; 1.0189x over previous
#include <cuda_runtime.h>
#include <cuda_bf16.h>
#include <math.h>
#include <stdint.h>

#define N_PROP 1024
#define C_FEAT 32
#define ROI 7
#define SR 6
#define SS 42
#define D_FEAT 1568
#define HID 2048
#define NMS_K 100
#define OUT_TOTAL 2600
#define NMS_THRF 0.01f
#define IMG_H 360
#define IMG_W 1200
#define BEV_H 700
#define BEV_W 800
#define IMG_HW (IMG_H * IMG_W)
#define BEV_HW (BEV_H * BEV_W)
#define X_MIN (-40.0f)
#define Z_MAX (70.0f)
#define VOX (0.1f)

__device__ float g_imgbox[N_PROP * 4];
__device__ float g_bevbox[N_PROP * 4];
__device__ float g_imgT[IMG_HW * C_FEAT];
__device__ float g_bevT[BEV_HW * C_FEAT];
__device__ float g_roiA[N_PROP * D_FEAT];
__device__ float g_roiB[N_PROP * D_FEAT];
__device__ float g_h2[N_PROP * HID];
__device__ float g_heads[N_PROP * 14];
__device__ float g_obj_soft[N_PROP * 2];
__device__ float g_pred[N_PROP * 6];
__device__ float g_predbev[N_PROP * 4];
__device__ float g_scores[N_PROP];
__device__ float g_orient[N_PROP];
__device__ int   g_idx[NMS_K];

__device__ unsigned short g_W1h[D_FEAT * HID];
__device__ unsigned short g_W1l[D_FEAT * HID];
__device__ unsigned short g_W2h[HID * HID];
__device__ unsigned short g_W2l[HID * HID];
__device__ unsigned short g_A1h[N_PROP * D_FEAT];
__device__ unsigned short g_A1l[N_PROP * D_FEAT];
__device__ unsigned short g_H1h[N_PROP * HID];
__device__ unsigned short g_H1l[N_PROP * HID];

__device__ __forceinline__ uint32_t smem_u32(const void* p) {
    uint32_t a;
    asm("{ .reg .u64 t; cvta.to.shared.u64 t, %1; cvt.u32.u64 %0, t; }" : "=r"(a) : "l"(p));
    return a;
}
#define CP16(d, s) asm volatile("cp.async.cg.shared.global [%0], [%1], 16;" :: "r"(d), "l"(s))
#define CP_COMMIT() asm volatile("cp.async.commit_group;" ::: "memory")
#define CP_WAIT_0() asm volatile("cp.async.wait_group 0;" ::: "memory")
#define CP_WAIT_1() asm volatile("cp.async.wait_group 1;" ::: "memory")

#define LDSM_X4(r0, r1, r2, r3, a) \
    asm volatile("ldmatrix.sync.aligned.m8n8.x4.shared.b16 {%0,%1,%2,%3}, [%4];" \
        : "=r"(r0), "=r"(r1), "=r"(r2), "=r"(r3) : "r"(a))
#define LDSM_X4T(r0, r1, r2, r3, a) \
    asm volatile("ldmatrix.sync.aligned.m8n8.x4.trans.shared.b16 {%0,%1,%2,%3}, [%4];" \
        : "=r"(r0), "=r"(r1), "=r"(r2), "=r"(r3) : "r"(a))
#define MMA16816(c, a0, a1, a2, a3, b0, b1) \
    asm volatile("mma.sync.aligned.m16n8k16.row.col.f32.bf16.bf16.f32 " \
        "{%0,%1,%2,%3}, {%4,%5,%6,%7}, {%8,%9}, {%0,%1,%2,%3};" \
        : "+f"((c)[0]), "+f"((c)[1]), "+f"((c)[2]), "+f"((c)[3]) \
        : "r"(a0), "r"(a1), "r"(a2), "r"(a3), "r"(b0), "r"(b1))

__device__ __forceinline__ void bsplit(float x, unsigned short& h, unsigned short& l) {
    __nv_bfloat16 bh = __float2bfloat16(x);
    float r = x - __bfloat162float(bh);
    __nv_bfloat16 bl = __float2bfloat16(r);
    h = *reinterpret_cast<unsigned short*>(&bh);
    l = *reinterpret_cast<unsigned short*>(&bl);
}

// ---------------- projections -------------------------------------------------
__global__ void project_kernel(const float* __restrict__ anchors,
                               const float* __restrict__ calib,
                               const int* __restrict__ image_shape)
{
    int n = blockIdx.x * blockDim.x + threadIdx.x;
    if (n >= N_PROP) return;
    const float* a = anchors + n * 6;
    float x = a[0], y = a[1], z = a[2];
    float dx = a[3], dy = a[4], dz = a[5];
    g_bevbox[n*4+0] = (x - dx*0.5f - X_MIN) / VOX;
    g_bevbox[n*4+1] = (Z_MAX - (z + dz*0.5f)) / VOX;
    g_bevbox[n*4+2] = (x + dx*0.5f - X_MIN) / VOX;
    g_bevbox[n*4+3] = (Z_MAX - (z - dz*0.5f)) / VOX;

    float P[12];
#pragma unroll
    for (int i = 0; i < 12; i++) P[i] = calib[i];
    float Hf = (float)image_shape[0];
    float Wf = (float)image_shape[1];
    float umin = 1e30f, umax = -1e30f, vmin = 1e30f, vmax = -1e30f;
#pragma unroll
    for (int k = 0; k < 8; k++) {
        float sx = (k & 4) ? 1.f : -1.f;
        float sy = (k & 2) ? 1.f : -1.f;
        float sz = (k & 1) ? 1.f : -1.f;
        float cx = x + sx * dx * 0.5f;
        float cy = y + sy * dy * 0.5f;
        float cz = z + sz * dz * 0.5f;
        float px = P[0]*cx + P[1]*cy + P[2]*cz + P[3];
        float py = P[4]*cx + P[5]*cy + P[6]*cz + P[7];
        float pz = P[8]*cx + P[9]*cy + P[10]*cz + P[11];
        float zz = fmaxf(pz, 0.1f);
        float u = px / zz, v = py / zz;
        umin = fminf(umin, u); umax = fmaxf(umax, u);
        vmin = fminf(vmin, v); vmax = fmaxf(vmax, v);
    }
    g_imgbox[n*4+0] = fminf(fmaxf(umin, 0.f), Wf);
    g_imgbox[n*4+1] = fminf(fmaxf(vmin, 0.f), Hf);
    g_imgbox[n*4+2] = fminf(fmaxf(umax, 0.f), Wf);
    g_imgbox[n*4+3] = fminf(fmaxf(vmax, 0.f), Hf);
}

// ---------------- CHW -> HWC transpose ----------------------------------------
#define IMG_TILES (IMG_HW / 64)
#define BEV_TILES (BEV_HW / 64)
__global__ void transpose_kernel(const float* __restrict__ img,
                                 const float* __restrict__ bev)
{
    int b = blockIdx.x;
    const float* src;
    float* dst;
    int HW, p0;
    if (b < IMG_TILES) { src = img; dst = g_imgT; HW = IMG_HW; p0 = b * 64; }
    else               { src = bev; dst = g_bevT; HW = BEV_HW; p0 = (b - IMG_TILES) * 64; }
    __shared__ float tile[32][65];
    int t = threadIdx.x;
#pragma unroll
    for (int i = 0; i < 2; i++) {
        int idx = t + i * 256;
        int c = idx >> 4, v4 = idx & 15;
        float4 v = *reinterpret_cast<const float4*>(src + (size_t)c * HW + p0 + v4 * 4);
        tile[c][v4*4+0] = v.x; tile[c][v4*4+1] = v.y;
        tile[c][v4*4+2] = v.z; tile[c][v4*4+3] = v.w;
    }
    __syncthreads();
#pragma unroll
    for (int i = 0; i < 2; i++) {
        int idx = t + i * 256;
        int p = idx >> 3, c4 = idx & 7;
        float4 v;
        v.x = tile[c4*4+0][p]; v.y = tile[c4*4+1][p];
        v.z = tile[c4*4+2][p]; v.w = tile[c4*4+3][p];
        *reinterpret_cast<float4*>(dst + (size_t)(p0 + p) * 32 + c4 * 4) = v;
    }
}

// ---------------- ROI align: 2048 blocks, reg LUT + packed coords (R13) --------
__global__ void roi_kernel()
{
    int b = blockIdx.x;
    int isImg = (b < N_PROP);
    int n = b & (N_PROP - 1);

    const float* ft    = isImg ? g_imgT : g_bevT;
    const float* boxes = isImg ? g_imgbox : g_bevbox;
    float* outp        = isImg ? g_roiA : g_roiB;
    int H = isImg ? IMG_H : BEV_H;
    int W = isImg ? IMG_W : BEV_W;

    __shared__ int2  sxp[SS];
    __shared__ int2  syp[SS];
    __shared__ float swx[SS], swy[SS];
    __shared__ float sout[D_FEAT];
    int t = threadIdx.x;
    int warp = t >> 5, lane = t & 31;
    int sg = lane >> 3;
    int c4 = (lane & 7) * 4;

    if (t < SS) {
        float bx1 = boxes[n*4+0] - 0.5f;
        float bx2 = boxes[n*4+2] - 0.5f;
        float g = ((float)t + 0.5f) / (float)SS;
        float xs = bx1 + g * (bx2 - bx1);
        float xf = fminf(fmaxf(floorf(xs), 0.f), (float)(W - 1));
        swx[t] = fminf(fmaxf(xs - xf, 0.f), 1.f);
        int xi = (int)xf;
        sxp[t] = make_int2(xi * 32, min(xi + 1, W - 1) * 32);
    } else if (t < 2 * SS) {
        int tt = t - SS;
        float by1 = boxes[n*4+1] - 0.5f;
        float by2 = boxes[n*4+3] - 0.5f;
        float g = ((float)tt + 0.5f) / (float)SS;
        float ys = by1 + g * (by2 - by1);
        float yf = fminf(fmaxf(floorf(ys), 0.f), (float)(H - 1));
        swy[tt] = fminf(fmaxf(ys - yf, 0.f), 1.f);
        int yi = (int)yf;
        syp[tt] = make_int2(yi * W * 32, min(yi + 1, H - 1) * W * 32);
    }

    int liy[9], lix[9];
#pragma unroll
    for (int it = 0; it < 9; it++) {
        int s = it * 4 + sg;
        liy[it] = s / SR;
        lix[it] = s - liy[it] * SR;
    }
    __syncthreads();

    const float* fb = ft + c4;
    for (int bin = warp; bin < ROI * ROI; bin += 8) {
        int py = (bin / ROI) * SR;
        int px = (bin % ROI) * SR;
        float ax = 0.f, ay = 0.f, az = 0.f, aw = 0.f;
#pragma unroll
        for (int it = 0; it < 9; it++) {
            int gy = py + liy[it], gx = px + lix[it];
            int2 ro = syp[gy];
            float wy = swy[gy];
            int2 xx = sxp[gx];
            float wx = swx[gx];
            float4 f00 = *reinterpret_cast<const float4*>(fb + ro.x + xx.x);
            float4 f01 = *reinterpret_cast<const float4*>(fb + ro.x + xx.y);
            float4 f10 = *reinterpret_cast<const float4*>(fb + ro.y + xx.x);
            float4 f11 = *reinterpret_cast<const float4*>(fb + ro.y + xx.y);
            float tx0, bx0;
            tx0 = fmaf(f01.x - f00.x, wx, f00.x);
            bx0 = fmaf(f11.x - f10.x, wx, f10.x);
            ax += fmaf(bx0 - tx0, wy, tx0);
            tx0 = fmaf(f01.y - f00.y, wx, f00.y);
            bx0 = fmaf(f11.y - f10.y, wx, f10.y);
            ay += fmaf(bx0 - tx0, wy, tx0);
            tx0 = fmaf(f01.z - f00.z, wx, f00.z);
            bx0 = fmaf(f11.z - f10.z, wx, f10.z);
            az += fmaf(bx0 - tx0, wy, tx0);
            tx0 = fmaf(f01.w - f00.w, wx, f00.w);
            bx0 = fmaf(f11.w - f10.w, wx, f10.w);
            aw += fmaf(bx0 - tx0, wy, tx0);
        }
#pragma unroll
        for (int off = 16; off >= 8; off >>= 1) {
            ax += __shfl_down_sync(0xffffffffu, ax, off);
            ay += __shfl_down_sync(0xffffffffu, ay, off);
            az += __shfl_down_sync(0xffffffffu, az, off);
            aw += __shfl_down_sync(0xffffffffu, aw, off);
        }
        if (lane < 8) {
            int ch = lane * 4;
            sout[(ch+0) * 49 + bin] = ax * (1.f / 36.f);
            sout[(ch+1) * 49 + bin] = ay * (1.f / 36.f);
            sout[(ch+2) * 49 + bin] = az * (1.f / 36.f);
            sout[(ch+3) * 49 + bin] = aw * (1.f / 36.f);
        }
    }
    __syncthreads();

    float* dst = outp + (size_t)n * D_FEAT;
    for (int idx = t; idx < D_FEAT; idx += 256)
        dst[idx] = sout[idx];
}

// ---------------- fuse + bf16 split (roiA, roiB -> A1h/A1l) --------------------
#define PA_N (N_PROP * D_FEAT / 4)
__global__ void prep_ab_kernel(const float* __restrict__ mi,
                               const float* __restrict__ mb)
{
    int i = blockIdx.x * blockDim.x + threadIdx.x;
    if (i >= PA_N) return;
    float ma = mi[0], mbv = mb[0];
    float inv = 1.f / (ma + mbv);
    float4 a = reinterpret_cast<const float4*>(g_roiA)[i];
    float4 bb = reinterpret_cast<const float4*>(g_roiB)[i];
    float4 v;
    v.x = (a.x * ma + bb.x * mbv) * inv;
    v.y = (a.y * ma + bb.y * mbv) * inv;
    v.z = (a.z * ma + bb.z * mbv) * inv;
    v.w = (a.w * ma + bb.w * mbv) * inv;
    unsigned short h0, l0, h1, l1, h2, l2, h3, l3;
    bsplit(v.x, h0, l0); bsplit(v.y, h1, l1);
    bsplit(v.z, h2, l2); bsplit(v.w, h3, l3);
    uint2 ph = { (uint32_t)h0 | ((uint32_t)h1 << 16), (uint32_t)h2 | ((uint32_t)h3 << 16) };
    uint2 pl = { (uint32_t)l0 | ((uint32_t)l1 << 16), (uint32_t)l2 | ((uint32_t)l3 << 16) };
    reinterpret_cast<uint2*>(g_A1h)[i] = ph;
    reinterpret_cast<uint2*>(g_A1l)[i] = pl;
}

// ---------------- weight split prep --------------------------------------------
#define PW_N1 (D_FEAT * HID / 4)
#define PW_N2 (HID * HID / 4)
__global__ void prep_w_kernel(const float* __restrict__ W1, const float* __restrict__ W2)
{
    int i = blockIdx.x * blockDim.x + threadIdx.x;
    const float4* src;
    unsigned short *dh, *dl;
    int idx;
    if (i < PW_N1) {
        src = reinterpret_cast<const float4*>(W1);
        dh = g_W1h; dl = g_W1l; idx = i;
    } else if (i < PW_N1 + PW_N2) {
        src = reinterpret_cast<const float4*>(W2);
        dh = g_W2h; dl = g_W2l; idx = i - PW_N1;
    } else return;
    float4 v = src[idx];
    unsigned short h0, l0, h1, l1, h2, l2, h3, l3;
    bsplit(v.x, h0, l0); bsplit(v.y, h1, l1);
    bsplit(v.z, h2, l2); bsplit(v.w, h3, l3);
    uint2 ph = { (uint32_t)h0 | ((uint32_t)h1 << 16), (uint32_t)h2 | ((uint32_t)h3 << 16) };
    uint2 pl = { (uint32_t)l0 | ((uint32_t)l1 << 16), (uint32_t)l2 | ((uint32_t)l3 << 16) };
    reinterpret_cast<uint2*>(dh)[idx] = ph;
    reinterpret_cast<uint2*>(dl)[idx] = pl;
}

// ---------------- HMMA bf16x3 GEMM, 3-stage cp.async ring ----------------------
#define GA_ST 10240
#define GB_ST 4608
#define OFF_AH 0
#define OFF_AL (3 * GA_ST)
#define OFF_BH (6 * GA_ST)
#define OFF_BL (6 * GA_ST + 3 * GB_ST)
#define GEMM_SMEM (6 * GA_ST + 6 * GB_ST)

template<int SPLIT_OUT>
__global__ __launch_bounds__(256)
void mma_gemm(const unsigned short* __restrict__ Ah, const unsigned short* __restrict__ Al,
              const unsigned short* __restrict__ Wh, const unsigned short* __restrict__ Wl,
              const float* __restrict__ bias, float* __restrict__ C,
              unsigned short* __restrict__ Oh, unsigned short* __restrict__ Ol, int K)
{
    extern __shared__ char smem[];
    uint32_t sb = smem_u32(smem);
    int tid = threadIdx.x;
    int wid = tid >> 5, lane = tid & 31;
    int wm = wid >> 2, wn = wid & 3;
    int m0 = blockIdx.y * 128, n0 = blockIdx.x * 64;

    int a_row0 = tid >> 2, a_seg0 = tid & 3;
    int a_row1 = (tid + 256) >> 2, a_seg1 = (tid + 256) & 3;
    int b_kk = tid >> 3;
    int b_ch = (tid & 7) << 3;

    float acc[4][2][4];
#pragma unroll
    for (int i = 0; i < 4; i++)
#pragma unroll
        for (int j = 0; j < 2; j++)
#pragma unroll
            for (int r = 0; r < 4; r++) acc[i][j][r] = 0.f;

    int ntiles = K / 32;

    auto issue = [&](int k0, int stage) {
        uint32_t ah = sb + OFF_AH + stage * GA_ST;
        uint32_t al = sb + OFF_AL + stage * GA_ST;
        CP16(ah + a_row0 * 80 + a_seg0 * 16, Ah + (size_t)(m0 + a_row0) * K + k0 + a_seg0 * 8);
        CP16(ah + a_row1 * 80 + a_seg1 * 16, Ah + (size_t)(m0 + a_row1) * K + k0 + a_seg1 * 8);
        CP16(al + a_row0 * 80 + a_seg0 * 16, Al + (size_t)(m0 + a_row0) * K + k0 + a_seg0 * 8);
        CP16(al + a_row1 * 80 + a_seg1 * 16, Al + (size_t)(m0 + a_row1) * K + k0 + a_seg1 * 8);
        uint32_t boff = (uint32_t)(b_kk * 144 + b_ch * 2);
        CP16(sb + OFF_BH + stage * GB_ST + boff, Wh + (size_t)(k0 + b_kk) * HID + n0 + b_ch);
        CP16(sb + OFF_BL + stage * GB_ST + boff, Wl + (size_t)(k0 + b_kk) * HID + n0 + b_ch);
        CP_COMMIT();
    };

    issue(0, 0);
    if (ntiles > 1) issue(32, 1);

    int lr = lane & 15;
    int lhalf = (lane >> 4) << 3;

    for (int t = 0; t < ntiles; t++) {
        // wait for group t: allow only the newest (t+1) to remain pending
        if (t + 1 < ntiles) { CP_WAIT_1(); } else { CP_WAIT_0(); }
        __syncthreads();
        if (t + 2 < ntiles) issue((t + 2) * 32, (t + 2) % 3);

        int stage = t % 3;
        uint32_t aH = sb + OFF_AH + stage * GA_ST;
        uint32_t aL = sb + OFF_AL + stage * GA_ST;
        uint32_t bH = sb + OFF_BH + stage * GB_ST;
        uint32_t bL = sb + OFF_BL + stage * GB_ST;

#pragma unroll
        for (int ks = 0; ks < 2; ks++) {
            uint32_t bo = (uint32_t)((ks * 16 + lr) * 144 + (wn * 16 + lhalf) * 2);
            uint32_t bh0, bh1, bh2, bh3, bl0, bl1, bl2, bl3;
            LDSM_X4T(bh0, bh1, bh2, bh3, bH + bo);
            LDSM_X4T(bl0, bl1, bl2, bl3, bL + bo);
#pragma unroll
            for (int mt = 0; mt < 4; mt++) {
                uint32_t ao = (uint32_t)((wm * 64 + mt * 16 + lr) * 80 +
                                         (ks * 16 + lhalf) * 2);
                uint32_t ah0, ah1, ah2, ah3, al0, al1, al2, al3;
                LDSM_X4(ah0, ah1, ah2, ah3, aH + ao);
                LDSM_X4(al0, al1, al2, al3, aL + ao);
                MMA16816(acc[mt][0], ah0, ah1, ah2, ah3, bh0, bh1);
                MMA16816(acc[mt][1], ah0, ah1, ah2, ah3, bh2, bh3);
                MMA16816(acc[mt][0], ah0, ah1, ah2, ah3, bl0, bl1);
                MMA16816(acc[mt][1], ah0, ah1, ah2, ah3, bl2, bl3);
                MMA16816(acc[mt][0], al0, al1, al2, al3, bh0, bh1);
                MMA16816(acc[mt][1], al0, al1, al2, al3, bh2, bh3);
            }
        }
    }

#pragma unroll
    for (int mt = 0; mt < 4; mt++) {
        int r = m0 + wm * 64 + mt * 16 + (lane >> 2);
#pragma unroll
        for (int nt = 0; nt < 2; nt++) {
            int c = n0 + wn * 16 + nt * 8 + 2 * (lane & 3);
            float2 bv = *reinterpret_cast<const float2*>(bias + c);
            float v00 = fmaxf(acc[mt][nt][0] + bv.x, 0.f);
            float v01 = fmaxf(acc[mt][nt][1] + bv.y, 0.f);
            float v10 = fmaxf(acc[mt][nt][2] + bv.x, 0.f);
            float v11 = fmaxf(acc[mt][nt][3] + bv.y, 0.f);
            if (SPLIT_OUT) {
                unsigned short h0, l0, h1, l1;
                bsplit(v00, h0, l0); bsplit(v01, h1, l1);
                *reinterpret_cast<uint32_t*>(Oh + (size_t)r * HID + c) =
                    (uint32_t)h0 | ((uint32_t)h1 << 16);
                *reinterpret_cast<uint32_t*>(Ol + (size_t)r * HID + c) =
                    (uint32_t)l0 | ((uint32_t)l1 << 16);
                bsplit(v10, h0, l0); bsplit(v11, h1, l1);
                *reinterpret_cast<uint32_t*>(Oh + (size_t)(r + 8) * HID + c) =
                    (uint32_t)h0 | ((uint32_t)h1 << 16);
                *reinterpret_cast<uint32_t*>(Ol + (size_t)(r + 8) * HID + c) =
                    (uint32_t)l0 | ((uint32_t)l1 << 16);
            } else {
                float2 o0 = {v00, v01}, o1 = {v10, v11};
                *reinterpret_cast<float2*>(C + (size_t)r * HID + c) = o0;
                *reinterpret_cast<float2*>(C + (size_t)(r + 8) * HID + c) = o1;
            }
        }
    }
}

// ---------------- heads --------------------------------------------------------
__global__ void heads_kernel(const float* __restrict__ Wc, const float* __restrict__ bc,
                             const float* __restrict__ Wo, const float* __restrict__ bo,
                             const float* __restrict__ Wa, const float* __restrict__ ba)
{
    int warp = threadIdx.x >> 5;
    int lane = threadIdx.x & 31;
    int row = blockIdx.x * 8 + warp;
    const float2* Wc2 = reinterpret_cast<const float2*>(Wc);
    const float2* Wo2 = reinterpret_cast<const float2*>(Wo);
    const float2* Wa2 = reinterpret_cast<const float2*>(Wa);
    float acc[14];
#pragma unroll
    for (int c = 0; c < 14; c++) acc[c] = 0.f;
    const float* h = g_h2 + (size_t)row * HID;
    for (int k = lane; k < HID; k += 32) {
        float hv = h[k];
        float2 cw = Wc2[k];
        acc[0] = fmaf(hv, cw.x, acc[0]);
        acc[1] = fmaf(hv, cw.y, acc[1]);
        const float2* wo = Wo2 + (size_t)k * 5;
#pragma unroll
        for (int j = 0; j < 5; j++) {
            float2 ov = wo[j];
            acc[2 + 2*j]     = fmaf(hv, ov.x, acc[2 + 2*j]);
            acc[2 + 2*j + 1] = fmaf(hv, ov.y, acc[2 + 2*j + 1]);
        }
        float2 aw = Wa2[k];
        acc[12] = fmaf(hv, aw.x, acc[12]);
        acc[13] = fmaf(hv, aw.y, acc[13]);
    }
#pragma unroll
    for (int c = 0; c < 14; c++) {
#pragma unroll
        for (int off = 16; off > 0; off >>= 1)
            acc[c] += __shfl_down_sync(0xffffffffu, acc[c], off);
    }
    if (lane == 0) {
#pragma unroll
        for (int c = 0; c < 14; c++) {
            float b = (c < 2) ? bc[c] : (c < 12 ? bo[c-2] : ba[c-12]);
            g_heads[row*14 + c] = acc[c] + b;
        }
    }
}

// ---------------- post ----------------------------------------------------------
__global__ void post_kernel(const float* __restrict__ anchors)
{
    int n = blockIdx.x * blockDim.x + threadIdx.x;
    if (n >= N_PROP) return;
    const float* hd = g_heads + n * 14;
    float o0 = hd[0], o1 = hd[1];
    float m = fmaxf(o0, o1);
    float e0 = expf(o0 - m), e1 = expf(o1 - m);
    float inv = 1.f / (e0 + e1);
    g_obj_soft[n*2+0] = e0 * inv;
    g_obj_soft[n*2+1] = e1 * inv;
    g_scores[n] = o1;
    g_orient[n] = atan2f(hd[13], hd[12]);
    float p[6];
#pragma unroll
    for (int i = 0; i < 6; i++) {
        p[i] = anchors[n*6+i] + hd[2+i];
        g_pred[n*6+i] = p[i];
    }
    float x = p[0], z = p[2], dx = p[3], dz = p[5];
    g_predbev[n*4+0] = (x - dx*0.5f - X_MIN) / VOX;
    g_predbev[n*4+1] = (Z_MAX - (z + dz*0.5f)) / VOX;
    g_predbev[n*4+2] = (x + dx*0.5f - X_MIN) / VOX;
    g_predbev[n*4+3] = (Z_MAX - (z - dz*0.5f)) / VOX;
}

// ---------------- NMS -----------------------------------------------------------
__global__ void nms_kernel()
{
    int t = threadIdx.x;
    __shared__ float ss[N_PROP];
    __shared__ float sval[8];
    __shared__ int   sidx[8];
    __shared__ float sb[4];
    __shared__ int   scur;
    float bx1[4], by1[4], bx2[4], by2[4], bar[4];
#pragma unroll
    for (int i = 0; i < 4; i++) {
        int b = t + i * 256;
        bx1[i] = g_predbev[b*4+0];
        by1[i] = g_predbev[b*4+1];
        bx2[i] = g_predbev[b*4+2];
        by2[i] = g_predbev[b*4+3];
        bar[i] = (bx2[i] - bx1[i]) * (by2[i] - by1[i]);
        ss[b] = g_scores[b];
    }
    __syncthreads();
    int warp = t >> 5, lane = t & 31;
    for (int k = 0; k < NMS_K; k++) {
        float v = -INFINITY;
        int bi = N_PROP;
#pragma unroll
        for (int i = 0; i < 4; i++) {
            int b = t + i * 256;
            float s = ss[b];
            if (s > v) { v = s; bi = b; }
        }
#pragma unroll
        for (int off = 16; off > 0; off >>= 1) {
            float ov = __shfl_down_sync(0xffffffffu, v, off);
            int   oi = __shfl_down_sync(0xffffffffu, bi, off);
            if (ov > v || (ov == v && oi < bi)) { v = ov; bi = oi; }
        }
        if (lane == 0) { sval[warp] = v; sidx[warp] = bi; }
        __syncthreads();
        if (t < 8) {
            v = sval[t]; bi = sidx[t];
#pragma unroll
            for (int off = 4; off > 0; off >>= 1) {
                float ov = __shfl_down_sync(0xffu, v, off, 8);
                int   oi = __shfl_down_sync(0xffu, bi, off, 8);
                if (ov > v || (ov == v && oi < bi)) { v = ov; bi = oi; }
            }
            if (t == 0) {
                scur = bi;
                g_idx[k] = bi;
                sb[0] = g_predbev[bi*4+0];
                sb[1] = g_predbev[bi*4+1];
                sb[2] = g_predbev[bi*4+2];
                sb[3] = g_predbev[bi*4+3];
            }
        }
        __syncthreads();
        float px1 = sb[0], py1 = sb[1], px2 = sb[2], py2 = sb[3];
        float parea = (px2 - px1) * (py2 - py1);
        int cur = scur;
#pragma unroll
        for (int i = 0; i < 4; i++) {
            int b = t + i * 256;
            float xx1 = fmaxf(bx1[i], px1);
            float yy1 = fmaxf(by1[i], py1);
            float xx2 = fminf(bx2[i], px2);
            float yy2 = fminf(by2[i], py2);
            float inter = fmaxf(xx2 - xx1, 0.f) * fmaxf(yy2 - yy1, 0.f);
            float iou = inter / (bar[i] + parea - inter + 1e-6f);
            if (iou > NMS_THRF || b == cur) ss[b] = -INFINITY;
        }
        __syncthreads();
    }
}

// ---------------- gather --------------------------------------------------------
__global__ void gather_kernel(float* __restrict__ out)
{
    int i = blockIdx.x * blockDim.x + threadIdx.x;
    if (i >= OUT_TOTAL) return;
    float v;
    if (i < 200) {
        int n = i / 2, c = i % 2;
        v = g_obj_soft[g_idx[n]*2 + c];
    } else if (i < 800) {
        int j = i - 200; int n = j / 6, c = j % 6;
        v = g_pred[g_idx[n]*6 + c];
    } else if (i < 1800) {
        int j = i - 800; int n = j / 10, c = j % 10;
        v = g_heads[g_idx[n]*14 + 2 + c];
    } else if (i < 2500) {
        int j = i - 1800; int n = j / 7, c = j % 7;
        v = (c < 6) ? g_pred[g_idx[n]*6 + c] : 0.f;
    } else {
        int n = i - 2500;
        v = g_orient[g_idx[n]];
    }
    out[i] = v;
}

// ---------------- launch ---------------------------------------------------------
extern "C" void kernel_launch(void* const* d_in, const int* in_sizes, int n_in,
                              void* d_out, int out_size)
{
    const float* img_feat = (const float*)d_in[0];
    const float* bev_feat = (const float*)d_in[1];
    const float* anchors  = (const float*)d_in[2];
    const float* calib    = (const float*)d_in[3];
    const float* img_mask = (const float*)d_in[5];
    const float* bev_mask = (const float*)d_in[6];
    const float* W1 = (const float*)d_in[7];
    const float* b1 = (const float*)d_in[8];
    const float* W2 = (const float*)d_in[9];
    const float* b2 = (const float*)d_in[10];
    const float* Wc = (const float*)d_in[11];
    const float* bc = (const float*)d_in[12];
    const float* Wo = (const float*)d_in[13];
    const float* bo = (const float*)d_in[14];
    const float* Wa = (const float*)d_in[15];
    const float* ba = (const float*)d_in[16];
    const int* image_shape = (const int*)d_in[17];
    float* out = (float*)d_out;

    void *pH2, *pW1h, *pW1l, *pW2h, *pW2l, *pA1h, *pA1l, *pH1h, *pH1l;
    cudaGetSymbolAddress(&pH2, g_h2);
    cudaGetSymbolAddress(&pW1h, g_W1h);
    cudaGetSymbolAddress(&pW1l, g_W1l);
    cudaGetSymbolAddress(&pW2h, g_W2h);
    cudaGetSymbolAddress(&pW2l, g_W2l);
    cudaGetSymbolAddress(&pA1h, g_A1h);
    cudaGetSymbolAddress(&pA1l, g_A1l);
    cudaGetSymbolAddress(&pH1h, g_H1h);
    cudaGetSymbolAddress(&pH1l, g_H1l);

    cudaFuncSetAttribute(mma_gemm<0>, cudaFuncAttributeMaxDynamicSharedMemorySize, GEMM_SMEM);
    cudaFuncSetAttribute(mma_gemm<1>, cudaFuncAttributeMaxDynamicSharedMemorySize, GEMM_SMEM);

    project_kernel<<<8, 128>>>(anchors, calib, image_shape);
    transpose_kernel<<<IMG_TILES + BEV_TILES, 256>>>(img_feat, bev_feat);
    prep_w_kernel<<<(PW_N1 + PW_N2 + 255) / 256, 256>>>(W1, W2);
    roi_kernel<<<2 * N_PROP, 256>>>();
    prep_ab_kernel<<<(PA_N + 255) / 256, 256>>>(img_mask, bev_mask);

    dim3 gg(HID / 64, N_PROP / 128);
    mma_gemm<1><<<gg, 256, GEMM_SMEM>>>(
        (const unsigned short*)pA1h, (const unsigned short*)pA1l,
        (const unsigned short*)pW1h, (const unsigned short*)pW1l,
        b1, nullptr, (unsigned short*)pH1h, (unsigned short*)pH1l, D_FEAT);
    mma_gemm<0><<<gg, 256, GEMM_SMEM>>>(
        (const unsigned short*)pH1h, (const unsigned short*)pH1l,
        (const unsigned short*)pW2h, (const unsigned short*)pW2l,
        b2, (float*)pH2, nullptr, nullptr, HID);

    heads_kernel<<<N_PROP / 8, 256>>>(Wc, bc, Wo, bo, Wa, ba);
    post_kernel<<<8, 128>>>(anchors);
    nms_kernel<<<1, 256>>>();
    gather_kernel<<<(OUT_TOTAL + 255) / 256, 256>>>(out);
}

// round 16
// speedup vs baseline: 1.0269x; 1.0079x over previous
#include <cuda_runtime.h>
#include <cuda_bf16.h>
#include <math.h>
#include <stdint.h>

#define N_PROP 1024
#define C_FEAT 32
#define ROI 7
#define SR 6
#define SS 42
#define D_FEAT 1568
#define HID 2048
#define NMS_K 100
#define OUT_TOTAL 2600
#define NMS_THRF 0.01f
#define IMG_H 360
#define IMG_W 1200
#define BEV_H 700
#define BEV_W 800
#define IMG_HW (IMG_H * IMG_W)
#define BEV_HW (BEV_H * BEV_W)
#define X_MIN (-40.0f)
#define Z_MAX (70.0f)
#define VOX (0.1f)

__device__ float g_imgbox[N_PROP * 4];
__device__ float g_bevbox[N_PROP * 4];
__device__ float g_imgT[IMG_HW * C_FEAT];
__device__ float g_bevT[BEV_HW * C_FEAT];
__device__ float g_roiA[N_PROP * D_FEAT];
__device__ float g_roiB[N_PROP * D_FEAT];
__device__ float g_h2[N_PROP * HID];
__device__ float g_heads[N_PROP * 14];
__device__ float g_obj_soft[N_PROP * 2];
__device__ float g_pred[N_PROP * 6];
__device__ float g_predbev[N_PROP * 4];
__device__ float g_scores[N_PROP];
__device__ float g_orient[N_PROP];

__device__ unsigned short g_W1h[D_FEAT * HID];
__device__ unsigned short g_W1l[D_FEAT * HID];
__device__ unsigned short g_W2h[HID * HID];
__device__ unsigned short g_W2l[HID * HID];
__device__ unsigned short g_A1h[N_PROP * D_FEAT];
__device__ unsigned short g_A1l[N_PROP * D_FEAT];
__device__ unsigned short g_H1h[N_PROP * HID];
__device__ unsigned short g_H1l[N_PROP * HID];

__device__ __forceinline__ uint32_t smem_u32(const void* p) {
    uint32_t a;
    asm("{ .reg .u64 t; cvta.to.shared.u64 t, %1; cvt.u32.u64 %0, t; }" : "=r"(a) : "l"(p));
    return a;
}
#define CP16(d, s) asm volatile("cp.async.cg.shared.global [%0], [%1], 16;" :: "r"(d), "l"(s))
#define CP_COMMIT() asm volatile("cp.async.commit_group;" ::: "memory")
#define CP_WAIT_0() asm volatile("cp.async.wait_group 0;" ::: "memory")

#define LDSM_X4(r0, r1, r2, r3, a) \
    asm volatile("ldmatrix.sync.aligned.m8n8.x4.shared.b16 {%0,%1,%2,%3}, [%4];" \
        : "=r"(r0), "=r"(r1), "=r"(r2), "=r"(r3) : "r"(a))
#define LDSM_X4T(r0, r1, r2, r3, a) \
    asm volatile("ldmatrix.sync.aligned.m8n8.x4.trans.shared.b16 {%0,%1,%2,%3}, [%4];" \
        : "=r"(r0), "=r"(r1), "=r"(r2), "=r"(r3) : "r"(a))
#define MMA16816(c, a0, a1, a2, a3, b0, b1) \
    asm volatile("mma.sync.aligned.m16n8k16.row.col.f32.bf16.bf16.f32 " \
        "{%0,%1,%2,%3}, {%4,%5,%6,%7}, {%8,%9}, {%0,%1,%2,%3};" \
        : "+f"((c)[0]), "+f"((c)[1]), "+f"((c)[2]), "+f"((c)[3]) \
        : "r"(a0), "r"(a1), "r"(a2), "r"(a3), "r"(b0), "r"(b1))

__device__ __forceinline__ void bsplit(float x, unsigned short& h, unsigned short& l) {
    __nv_bfloat16 bh = __float2bfloat16(x);
    float r = x - __bfloat162float(bh);
    __nv_bfloat16 bl = __float2bfloat16(r);
    h = *reinterpret_cast<unsigned short*>(&bh);
    l = *reinterpret_cast<unsigned short*>(&bl);
}

// ---------------- projections -------------------------------------------------
__global__ void project_kernel(const float* __restrict__ anchors,
                               const float* __restrict__ calib,
                               const int* __restrict__ image_shape)
{
    int n = blockIdx.x * blockDim.x + threadIdx.x;
    if (n >= N_PROP) return;
    const float* a = anchors + n * 6;
    float x = a[0], y = a[1], z = a[2];
    float dx = a[3], dy = a[4], dz = a[5];
    g_bevbox[n*4+0] = (x - dx*0.5f - X_MIN) / VOX;
    g_bevbox[n*4+1] = (Z_MAX - (z + dz*0.5f)) / VOX;
    g_bevbox[n*4+2] = (x + dx*0.5f - X_MIN) / VOX;
    g_bevbox[n*4+3] = (Z_MAX - (z - dz*0.5f)) / VOX;

    float P[12];
#pragma unroll
    for (int i = 0; i < 12; i++) P[i] = calib[i];
    float Hf = (float)image_shape[0];
    float Wf = (float)image_shape[1];
    float umin = 1e30f, umax = -1e30f, vmin = 1e30f, vmax = -1e30f;
#pragma unroll
    for (int k = 0; k < 8; k++) {
        float sx = (k & 4) ? 1.f : -1.f;
        float sy = (k & 2) ? 1.f : -1.f;
        float sz = (k & 1) ? 1.f : -1.f;
        float cx = x + sx * dx * 0.5f;
        float cy = y + sy * dy * 0.5f;
        float cz = z + sz * dz * 0.5f;
        float px = P[0]*cx + P[1]*cy + P[2]*cz + P[3];
        float py = P[4]*cx + P[5]*cy + P[6]*cz + P[7];
        float pz = P[8]*cx + P[9]*cy + P[10]*cz + P[11];
        float zz = fmaxf(pz, 0.1f);
        float u = px / zz, v = py / zz;
        umin = fminf(umin, u); umax = fmaxf(umax, u);
        vmin = fminf(vmin, v); vmax = fmaxf(vmax, v);
    }
    g_imgbox[n*4+0] = fminf(fmaxf(umin, 0.f), Wf);
    g_imgbox[n*4+1] = fminf(fmaxf(vmin, 0.f), Hf);
    g_imgbox[n*4+2] = fminf(fmaxf(umax, 0.f), Wf);
    g_imgbox[n*4+3] = fminf(fmaxf(vmax, 0.f), Hf);
}

// ---------------- CHW -> HWC transpose ----------------------------------------
#define IMG_TILES (IMG_HW / 64)
#define BEV_TILES (BEV_HW / 64)
__global__ void transpose_kernel(const float* __restrict__ img,
                                 const float* __restrict__ bev)
{
    int b = blockIdx.x;
    const float* src;
    float* dst;
    int HW, p0;
    if (b < IMG_TILES) { src = img; dst = g_imgT; HW = IMG_HW; p0 = b * 64; }
    else               { src = bev; dst = g_bevT; HW = BEV_HW; p0 = (b - IMG_TILES) * 64; }
    __shared__ float tile[32][65];
    int t = threadIdx.x;
#pragma unroll
    for (int i = 0; i < 2; i++) {
        int idx = t + i * 256;
        int c = idx >> 4, v4 = idx & 15;
        float4 v = *reinterpret_cast<const float4*>(src + (size_t)c * HW + p0 + v4 * 4);
        tile[c][v4*4+0] = v.x; tile[c][v4*4+1] = v.y;
        tile[c][v4*4+2] = v.z; tile[c][v4*4+3] = v.w;
    }
    __syncthreads();
#pragma unroll
    for (int i = 0; i < 2; i++) {
        int idx = t + i * 256;
        int p = idx >> 3, c4 = idx & 7;
        float4 v;
        v.x = tile[c4*4+0][p]; v.y = tile[c4*4+1][p];
        v.z = tile[c4*4+2][p]; v.w = tile[c4*4+3][p];
        *reinterpret_cast<float4*>(dst + (size_t)(p0 + p) * 32 + c4 * 4) = v;
    }
}

// ---------------- ROI align (R13-proven) ---------------------------------------
__global__ void roi_kernel()
{
    int b = blockIdx.x;
    int isImg = (b < N_PROP);
    int n = b & (N_PROP - 1);

    const float* ft    = isImg ? g_imgT : g_bevT;
    const float* boxes = isImg ? g_imgbox : g_bevbox;
    float* outp        = isImg ? g_roiA : g_roiB;
    int H = isImg ? IMG_H : BEV_H;
    int W = isImg ? IMG_W : BEV_W;

    __shared__ int2  sxp[SS];
    __shared__ int2  syp[SS];
    __shared__ float swx[SS], swy[SS];
    __shared__ float sout[D_FEAT];
    int t = threadIdx.x;
    int warp = t >> 5, lane = t & 31;
    int sg = lane >> 3;
    int c4 = (lane & 7) * 4;

    if (t < SS) {
        float bx1 = boxes[n*4+0] - 0.5f;
        float bx2 = boxes[n*4+2] - 0.5f;
        float g = ((float)t + 0.5f) / (float)SS;
        float xs = bx1 + g * (bx2 - bx1);
        float xf = fminf(fmaxf(floorf(xs), 0.f), (float)(W - 1));
        swx[t] = fminf(fmaxf(xs - xf, 0.f), 1.f);
        int xi = (int)xf;
        sxp[t] = make_int2(xi * 32, min(xi + 1, W - 1) * 32);
    } else if (t < 2 * SS) {
        int tt = t - SS;
        float by1 = boxes[n*4+1] - 0.5f;
        float by2 = boxes[n*4+3] - 0.5f;
        float g = ((float)tt + 0.5f) / (float)SS;
        float ys = by1 + g * (by2 - by1);
        float yf = fminf(fmaxf(floorf(ys), 0.f), (float)(H - 1));
        swy[tt] = fminf(fmaxf(ys - yf, 0.f), 1.f);
        int yi = (int)yf;
        syp[tt] = make_int2(yi * W * 32, min(yi + 1, H - 1) * W * 32);
    }

    int liy[9], lix[9];
#pragma unroll
    for (int it = 0; it < 9; it++) {
        int s = it * 4 + sg;
        liy[it] = s / SR;
        lix[it] = s - liy[it] * SR;
    }
    __syncthreads();

    const float* fb = ft + c4;
    for (int bin = warp; bin < ROI * ROI; bin += 8) {
        int py = (bin / ROI) * SR;
        int px = (bin % ROI) * SR;
        float ax = 0.f, ay = 0.f, az = 0.f, aw = 0.f;
#pragma unroll
        for (int it = 0; it < 9; it++) {
            int gy = py + liy[it], gx = px + lix[it];
            int2 ro = syp[gy];
            float wy = swy[gy];
            int2 xx = sxp[gx];
            float wx = swx[gx];
            float4 f00 = *reinterpret_cast<const float4*>(fb + ro.x + xx.x);
            float4 f01 = *reinterpret_cast<const float4*>(fb + ro.x + xx.y);
            float4 f10 = *reinterpret_cast<const float4*>(fb + ro.y + xx.x);
            float4 f11 = *reinterpret_cast<const float4*>(fb + ro.y + xx.y);
            float tx0, bx0;
            tx0 = fmaf(f01.x - f00.x, wx, f00.x);
            bx0 = fmaf(f11.x - f10.x, wx, f10.x);
            ax += fmaf(bx0 - tx0, wy, tx0);
            tx0 = fmaf(f01.y - f00.y, wx, f00.y);
            bx0 = fmaf(f11.y - f10.y, wx, f10.y);
            ay += fmaf(bx0 - tx0, wy, tx0);
            tx0 = fmaf(f01.z - f00.z, wx, f00.z);
            bx0 = fmaf(f11.z - f10.z, wx, f10.z);
            az += fmaf(bx0 - tx0, wy, tx0);
            tx0 = fmaf(f01.w - f00.w, wx, f00.w);
            bx0 = fmaf(f11.w - f10.w, wx, f10.w);
            aw += fmaf(bx0 - tx0, wy, tx0);
        }
#pragma unroll
        for (int off = 16; off >= 8; off >>= 1) {
            ax += __shfl_down_sync(0xffffffffu, ax, off);
            ay += __shfl_down_sync(0xffffffffu, ay, off);
            az += __shfl_down_sync(0xffffffffu, az, off);
            aw += __shfl_down_sync(0xffffffffu, aw, off);
        }
        if (lane < 8) {
            int ch = lane * 4;
            sout[(ch+0) * 49 + bin] = ax * (1.f / 36.f);
            sout[(ch+1) * 49 + bin] = ay * (1.f / 36.f);
            sout[(ch+2) * 49 + bin] = az * (1.f / 36.f);
            sout[(ch+3) * 49 + bin] = aw * (1.f / 36.f);
        }
    }
    __syncthreads();

    float* dst = outp + (size_t)n * D_FEAT;
    for (int idx = t; idx < D_FEAT; idx += 256)
        dst[idx] = sout[idx];
}

// ---------------- fuse + bf16 split --------------------------------------------
#define PA_N (N_PROP * D_FEAT / 4)
__global__ void prep_ab_kernel(const float* __restrict__ mi,
                               const float* __restrict__ mb)
{
    int i = blockIdx.x * blockDim.x + threadIdx.x;
    if (i >= PA_N) return;
    float ma = mi[0], mbv = mb[0];
    float inv = 1.f / (ma + mbv);
    float4 a = reinterpret_cast<const float4*>(g_roiA)[i];
    float4 bb = reinterpret_cast<const float4*>(g_roiB)[i];
    float4 v;
    v.x = (a.x * ma + bb.x * mbv) * inv;
    v.y = (a.y * ma + bb.y * mbv) * inv;
    v.z = (a.z * ma + bb.z * mbv) * inv;
    v.w = (a.w * ma + bb.w * mbv) * inv;
    unsigned short h0, l0, h1, l1, h2, l2, h3, l3;
    bsplit(v.x, h0, l0); bsplit(v.y, h1, l1);
    bsplit(v.z, h2, l2); bsplit(v.w, h3, l3);
    uint2 ph = { (uint32_t)h0 | ((uint32_t)h1 << 16), (uint32_t)h2 | ((uint32_t)h3 << 16) };
    uint2 pl = { (uint32_t)l0 | ((uint32_t)l1 << 16), (uint32_t)l2 | ((uint32_t)l3 << 16) };
    reinterpret_cast<uint2*>(g_A1h)[i] = ph;
    reinterpret_cast<uint2*>(g_A1l)[i] = pl;
}

// ---------------- weight split prep --------------------------------------------
#define PW_N1 (D_FEAT * HID / 4)
#define PW_N2 (HID * HID / 4)
__global__ void prep_w_kernel(const float* __restrict__ W1, const float* __restrict__ W2)
{
    int i = blockIdx.x * blockDim.x + threadIdx.x;
    const float4* src;
    unsigned short *dh, *dl;
    int idx;
    if (i < PW_N1) {
        src = reinterpret_cast<const float4*>(W1);
        dh = g_W1h; dl = g_W1l; idx = i;
    } else if (i < PW_N1 + PW_N2) {
        src = reinterpret_cast<const float4*>(W2);
        dh = g_W2h; dl = g_W2l; idx = i - PW_N1;
    } else return;
    float4 v = src[idx];
    unsigned short h0, l0, h1, l1, h2, l2, h3, l3;
    bsplit(v.x, h0, l0); bsplit(v.y, h1, l1);
    bsplit(v.z, h2, l2); bsplit(v.w, h3, l3);
    uint2 ph = { (uint32_t)h0 | ((uint32_t)h1 << 16), (uint32_t)h2 | ((uint32_t)h3 << 16) };
    uint2 pl = { (uint32_t)l0 | ((uint32_t)l1 << 16), (uint32_t)l2 | ((uint32_t)l3 << 16) };
    reinterpret_cast<uint2*>(dh)[idx] = ph;
    reinterpret_cast<uint2*>(dl)[idx] = pl;
}

// ---------------- HMMA bf16x3 GEMM, 2-stage (R11-proven) -----------------------
#define GA_ST 10240
#define GB_ST 4608
#define OFF_AH 0
#define OFF_AL (2 * GA_ST)
#define OFF_BH (4 * GA_ST)
#define OFF_BL (4 * GA_ST + 2 * GB_ST)
#define GEMM_SMEM (4 * GA_ST + 4 * GB_ST)

template<int SPLIT_OUT>
__global__ __launch_bounds__(256)
void mma_gemm(const unsigned short* __restrict__ Ah, const unsigned short* __restrict__ Al,
              const unsigned short* __restrict__ Wh, const unsigned short* __restrict__ Wl,
              const float* __restrict__ bias, float* __restrict__ C,
              unsigned short* __restrict__ Oh, unsigned short* __restrict__ Ol, int K)
{
    extern __shared__ char smem[];
    uint32_t sb = smem_u32(smem);
    int tid = threadIdx.x;
    int wid = tid >> 5, lane = tid & 31;
    int wm = wid >> 2, wn = wid & 3;
    int m0 = blockIdx.y * 128, n0 = blockIdx.x * 64;

    int a_row0 = tid >> 2, a_seg0 = tid & 3;
    int a_row1 = (tid + 256) >> 2, a_seg1 = (tid + 256) & 3;
    int b_kk = tid >> 3;
    int b_ch = (tid & 7) << 3;

    float acc[4][2][4];
#pragma unroll
    for (int i = 0; i < 4; i++)
#pragma unroll
        for (int j = 0; j < 2; j++)
#pragma unroll
            for (int r = 0; r < 4; r++) acc[i][j][r] = 0.f;

    int ntiles = K / 32;

    auto issue = [&](int k0, int stage) {
        uint32_t ah = sb + OFF_AH + stage * GA_ST;
        uint32_t al = sb + OFF_AL + stage * GA_ST;
        CP16(ah + a_row0 * 80 + a_seg0 * 16, Ah + (size_t)(m0 + a_row0) * K + k0 + a_seg0 * 8);
        CP16(ah + a_row1 * 80 + a_seg1 * 16, Ah + (size_t)(m0 + a_row1) * K + k0 + a_seg1 * 8);
        CP16(al + a_row0 * 80 + a_seg0 * 16, Al + (size_t)(m0 + a_row0) * K + k0 + a_seg0 * 8);
        CP16(al + a_row1 * 80 + a_seg1 * 16, Al + (size_t)(m0 + a_row1) * K + k0 + a_seg1 * 8);
        uint32_t boff = (uint32_t)(b_kk * 144 + b_ch * 2);
        CP16(sb + OFF_BH + stage * GB_ST + boff, Wh + (size_t)(k0 + b_kk) * HID + n0 + b_ch);
        CP16(sb + OFF_BL + stage * GB_ST + boff, Wl + (size_t)(k0 + b_kk) * HID + n0 + b_ch);
        CP_COMMIT();
    };

    issue(0, 0);
    CP_WAIT_0();
    __syncthreads();

    int lr = lane & 15;
    int lhalf = (lane >> 4) << 3;

    for (int t = 0; t < ntiles; t++) {
        int stage = t & 1;
        bool more = (t + 1 < ntiles);
        if (more) issue((t + 1) * 32, stage ^ 1);

        uint32_t aH = sb + OFF_AH + stage * GA_ST;
        uint32_t aL = sb + OFF_AL + stage * GA_ST;
        uint32_t bH = sb + OFF_BH + stage * GB_ST;
        uint32_t bL = sb + OFF_BL + stage * GB_ST;

#pragma unroll
        for (int ks = 0; ks < 2; ks++) {
            uint32_t bo = (uint32_t)((ks * 16 + lr) * 144 + (wn * 16 + lhalf) * 2);
            uint32_t bh0, bh1, bh2, bh3, bl0, bl1, bl2, bl3;
            LDSM_X4T(bh0, bh1, bh2, bh3, bH + bo);
            LDSM_X4T(bl0, bl1, bl2, bl3, bL + bo);
#pragma unroll
            for (int mt = 0; mt < 4; mt++) {
                uint32_t ao = (uint32_t)((wm * 64 + mt * 16 + lr) * 80 +
                                         (ks * 16 + lhalf) * 2);
                uint32_t ah0, ah1, ah2, ah3, al0, al1, al2, al3;
                LDSM_X4(ah0, ah1, ah2, ah3, aH + ao);
                LDSM_X4(al0, al1, al2, al3, aL + ao);
                MMA16816(acc[mt][0], ah0, ah1, ah2, ah3, bh0, bh1);
                MMA16816(acc[mt][1], ah0, ah1, ah2, ah3, bh2, bh3);
                MMA16816(acc[mt][0], ah0, ah1, ah2, ah3, bl0, bl1);
                MMA16816(acc[mt][1], ah0, ah1, ah2, ah3, bl2, bl3);
                MMA16816(acc[mt][0], al0, al1, al2, al3, bh0, bh1);
                MMA16816(acc[mt][1], al0, al1, al2, al3, bh2, bh3);
            }
        }

        if (more) {
            CP_WAIT_0();
            __syncthreads();
        }
    }

#pragma unroll
    for (int mt = 0; mt < 4; mt++) {
        int r = m0 + wm * 64 + mt * 16 + (lane >> 2);
#pragma unroll
        for (int nt = 0; nt < 2; nt++) {
            int c = n0 + wn * 16 + nt * 8 + 2 * (lane & 3);
            float2 bv = *reinterpret_cast<const float2*>(bias + c);
            float v00 = fmaxf(acc[mt][nt][0] + bv.x, 0.f);
            float v01 = fmaxf(acc[mt][nt][1] + bv.y, 0.f);
            float v10 = fmaxf(acc[mt][nt][2] + bv.x, 0.f);
            float v11 = fmaxf(acc[mt][nt][3] + bv.y, 0.f);
            if (SPLIT_OUT) {
                unsigned short h0, l0, h1, l1;
                bsplit(v00, h0, l0); bsplit(v01, h1, l1);
                *reinterpret_cast<uint32_t*>(Oh + (size_t)r * HID + c) =
                    (uint32_t)h0 | ((uint32_t)h1 << 16);
                *reinterpret_cast<uint32_t*>(Ol + (size_t)r * HID + c) =
                    (uint32_t)l0 | ((uint32_t)l1 << 16);
                bsplit(v10, h0, l0); bsplit(v11, h1, l1);
                *reinterpret_cast<uint32_t*>(Oh + (size_t)(r + 8) * HID + c) =
                    (uint32_t)h0 | ((uint32_t)h1 << 16);
                *reinterpret_cast<uint32_t*>(Ol + (size_t)(r + 8) * HID + c) =
                    (uint32_t)l0 | ((uint32_t)l1 << 16);
            } else {
                float2 o0 = {v00, v01}, o1 = {v10, v11};
                *reinterpret_cast<float2*>(C + (size_t)r * HID + c) = o0;
                *reinterpret_cast<float2*>(C + (size_t)(r + 8) * HID + c) = o1;
            }
        }
    }
}

// ---------------- heads + post (fused) ------------------------------------------
__global__ void heads_kernel(const float* __restrict__ Wc, const float* __restrict__ bc,
                             const float* __restrict__ Wo, const float* __restrict__ bo,
                             const float* __restrict__ Wa, const float* __restrict__ ba,
                             const float* __restrict__ anchors)
{
    int warp = threadIdx.x >> 5;
    int lane = threadIdx.x & 31;
    int row = blockIdx.x * 8 + warp;
    const float2* Wc2 = reinterpret_cast<const float2*>(Wc);
    const float2* Wo2 = reinterpret_cast<const float2*>(Wo);
    const float2* Wa2 = reinterpret_cast<const float2*>(Wa);
    float acc[14];
#pragma unroll
    for (int c = 0; c < 14; c++) acc[c] = 0.f;
    const float* h = g_h2 + (size_t)row * HID;
    for (int k = lane; k < HID; k += 32) {
        float hv = h[k];
        float2 cw = Wc2[k];
        acc[0] = fmaf(hv, cw.x, acc[0]);
        acc[1] = fmaf(hv, cw.y, acc[1]);
        const float2* wo = Wo2 + (size_t)k * 5;
#pragma unroll
        for (int j = 0; j < 5; j++) {
            float2 ov = wo[j];
            acc[2 + 2*j]     = fmaf(hv, ov.x, acc[2 + 2*j]);
            acc[2 + 2*j + 1] = fmaf(hv, ov.y, acc[2 + 2*j + 1]);
        }
        float2 aw = Wa2[k];
        acc[12] = fmaf(hv, aw.x, acc[12]);
        acc[13] = fmaf(hv, aw.y, acc[13]);
    }
#pragma unroll
    for (int c = 0; c < 14; c++) {
#pragma unroll
        for (int off = 16; off > 0; off >>= 1)
            acc[c] += __shfl_down_sync(0xffffffffu, acc[c], off);
    }
    if (lane == 0) {
        float hd[14];
#pragma unroll
        for (int c = 0; c < 14; c++) {
            float b = (c < 2) ? bc[c] : (c < 12 ? bo[c-2] : ba[c-12]);
            hd[c] = acc[c] + b;
            g_heads[row*14 + c] = hd[c];
        }
        // fused post
        float o0 = hd[0], o1 = hd[1];
        float m = fmaxf(o0, o1);
        float e0 = expf(o0 - m), e1 = expf(o1 - m);
        float inv = 1.f / (e0 + e1);
        g_obj_soft[row*2+0] = e0 * inv;
        g_obj_soft[row*2+1] = e1 * inv;
        g_scores[row] = o1;
        g_orient[row] = atan2f(hd[13], hd[12]);
        float p[6];
#pragma unroll
        for (int i = 0; i < 6; i++) {
            p[i] = anchors[row*6+i] + hd[2+i];
            g_pred[row*6+i] = p[i];
        }
        float x = p[0], z = p[2], dx = p[3], dz = p[5];
        g_predbev[row*4+0] = (x - dx*0.5f - X_MIN) / VOX;
        g_predbev[row*4+1] = (Z_MAX - (z + dz*0.5f)) / VOX;
        g_predbev[row*4+2] = (x + dx*0.5f - X_MIN) / VOX;
        g_predbev[row*4+3] = (Z_MAX - (z - dz*0.5f)) / VOX;
    }
}

// ---------------- NMS + gather (fused) -------------------------------------------
__global__ void nms_kernel(float* __restrict__ out)
{
    int t = threadIdx.x;
    __shared__ float ss[N_PROP];
    __shared__ float sval[8];
    __shared__ int   sidx[8];
    __shared__ float sb[4];
    __shared__ int   scur;
    __shared__ int   spicks[NMS_K];
    float bx1[4], by1[4], bx2[4], by2[4], bar[4];
#pragma unroll
    for (int i = 0; i < 4; i++) {
        int b = t + i * 256;
        bx1[i] = g_predbev[b*4+0];
        by1[i] = g_predbev[b*4+1];
        bx2[i] = g_predbev[b*4+2];
        by2[i] = g_predbev[b*4+3];
        bar[i] = (bx2[i] - bx1[i]) * (by2[i] - by1[i]);
        ss[b] = g_scores[b];
    }
    __syncthreads();
    int warp = t >> 5, lane = t & 31;
    for (int k = 0; k < NMS_K; k++) {
        float v = -INFINITY;
        int bi = N_PROP;
#pragma unroll
        for (int i = 0; i < 4; i++) {
            int b = t + i * 256;
            float s = ss[b];
            if (s > v) { v = s; bi = b; }
        }
#pragma unroll
        for (int off = 16; off > 0; off >>= 1) {
            float ov = __shfl_down_sync(0xffffffffu, v, off);
            int   oi = __shfl_down_sync(0xffffffffu, bi, off);
            if (ov > v || (ov == v && oi < bi)) { v = ov; bi = oi; }
        }
        if (lane == 0) { sval[warp] = v; sidx[warp] = bi; }
        __syncthreads();
        if (t < 8) {
            v = sval[t]; bi = sidx[t];
#pragma unroll
            for (int off = 4; off > 0; off >>= 1) {
                float ov = __shfl_down_sync(0xffu, v, off, 8);
                int   oi = __shfl_down_sync(0xffu, bi, off, 8);
                if (ov > v || (ov == v && oi < bi)) { v = ov; bi = oi; }
            }
            if (t == 0) {
                scur = bi;
                spicks[k] = bi;
                sb[0] = g_predbev[bi*4+0];
                sb[1] = g_predbev[bi*4+1];
                sb[2] = g_predbev[bi*4+2];
                sb[3] = g_predbev[bi*4+3];
            }
        }
        __syncthreads();
        float px1 = sb[0], py1 = sb[1], px2 = sb[2], py2 = sb[3];
        float parea = (px2 - px1) * (py2 - py1);
        int cur = scur;
#pragma unroll
        for (int i = 0; i < 4; i++) {
            int b = t + i * 256;
            float xx1 = fmaxf(bx1[i], px1);
            float yy1 = fmaxf(by1[i], py1);
            float xx2 = fminf(bx2[i], px2);
            float yy2 = fminf(by2[i], py2);
            float inter = fmaxf(xx2 - xx1, 0.f) * fmaxf(yy2 - yy1, 0.f);
            float iou = inter / (bar[i] + parea - inter + 1e-6f);
            if (iou > NMS_THRF || b == cur) ss[b] = -INFINITY;
        }
        __syncthreads();
    }

    // fused gather
    for (int i = t; i < OUT_TOTAL; i += 256) {
        float v;
        if (i < 200) {
            int n = i / 2, c = i % 2;
            v = g_obj_soft[spicks[n]*2 + c];
        } else if (i < 800) {
            int j = i - 200; int n = j / 6, c = j % 6;
            v = g_pred[spicks[n]*6 + c];
        } else if (i < 1800) {
            int j = i - 800; int n = j / 10, c = j % 10;
            v = g_heads[spicks[n]*14 + 2 + c];
        } else if (i < 2500) {
            int j = i - 1800; int n = j / 7, c = j % 7;
            v = (c < 6) ? g_pred[spicks[n]*6 + c] : 0.f;
        } else {
            int n = i - 2500;
            v = g_orient[spicks[n]];
        }
        out[i] = v;
    }
}

// ---------------- launch ---------------------------------------------------------
extern "C" void kernel_launch(void* const* d_in, const int* in_sizes, int n_in,
                              void* d_out, int out_size)
{
    const float* img_feat = (const float*)d_in[0];
    const float* bev_feat = (const float*)d_in[1];
    const float* anchors  = (const float*)d_in[2];
    const float* calib    = (const float*)d_in[3];
    const float* img_mask = (const float*)d_in[5];
    const float* bev_mask = (const float*)d_in[6];
    const float* W1 = (const float*)d_in[7];
    const float* b1 = (const float*)d_in[8];
    const float* W2 = (const float*)d_in[9];
    const float* b2 = (const float*)d_in[10];
    const float* Wc = (const float*)d_in[11];
    const float* bc = (const float*)d_in[12];
    const float* Wo = (const float*)d_in[13];
    const float* bo = (const float*)d_in[14];
    const float* Wa = (const float*)d_in[15];
    const float* ba = (const float*)d_in[16];
    const int* image_shape = (const int*)d_in[17];
    float* out = (float*)d_out;

    void *pH2, *pW1h, *pW1l, *pW2h, *pW2l, *pA1h, *pA1l, *pH1h, *pH1l;
    cudaGetSymbolAddress(&pH2, g_h2);
    cudaGetSymbolAddress(&pW1h, g_W1h);
    cudaGetSymbolAddress(&pW1l, g_W1l);
    cudaGetSymbolAddress(&pW2h, g_W2h);
    cudaGetSymbolAddress(&pW2l, g_W2l);
    cudaGetSymbolAddress(&pA1h, g_A1h);
    cudaGetSymbolAddress(&pA1l, g_A1l);
    cudaGetSymbolAddress(&pH1h, g_H1h);
    cudaGetSymbolAddress(&pH1l, g_H1l);

    cudaFuncSetAttribute(mma_gemm<0>, cudaFuncAttributeMaxDynamicSharedMemorySize, GEMM_SMEM);
    cudaFuncSetAttribute(mma_gemm<1>, cudaFuncAttributeMaxDynamicSharedMemorySize, GEMM_SMEM);

    project_kernel<<<8, 128>>>(anchors, calib, image_shape);
    transpose_kernel<<<IMG_TILES + BEV_TILES, 256>>>(img_feat, bev_feat);
    prep_w_kernel<<<(PW_N1 + PW_N2 + 255) / 256, 256>>>(W1, W2);
    roi_kernel<<<2 * N_PROP, 256>>>();
    prep_ab_kernel<<<(PA_N + 255) / 256, 256>>>(img_mask, bev_mask);

    dim3 gg(HID / 64, N_PROP / 128);
    mma_gemm<1><<<gg, 256, GEMM_SMEM>>>(
        (const unsigned short*)pA1h, (const unsigned short*)pA1l,
        (const unsigned short*)pW1h, (const unsigned short*)pW1l,
        b1, nullptr, (unsigned short*)pH1h, (unsigned short*)pH1l, D_FEAT);
    mma_gemm<0><<<gg, 256, GEMM_SMEM>>>(
        (const unsigned short*)pH1h, (const unsigned short*)pH1l,
        (const unsigned short*)pW2h, (const unsigned short*)pW2l,
        b2, (float*)pH2, nullptr, nullptr, HID);

    heads_kernel<<<N_PROP / 8, 256>>>(Wc, bc, Wo, bo, Wa, ba, anchors);
    nms_kernel<<<1, 256>>>(out);
}